// round 7
// baseline (speedup 1.0000x reference)
#include <cuda_runtime.h>
#include <cuda_fp16.h>
#include <stdint.h>

#define N_NODES 100000
#define N_FEATS 256
#define OUT_DIM 64
#define NNZ_X   1280000
#define N_EDGES 1600000
#define M_PAD   100032            // 1563 * 64, exact grid cover

// scan config: 256 threads x 8 elems = 2048 per block
#define SCAN_BS 256
#define SCAN_EL 8
#define SCAN_CHUNK (SCAN_BS * SCAN_EL)
#define SCANA_NB ((N_NODES + SCAN_CHUNK - 1) / SCAN_CHUNK)   // 49

// GEMM tiling
#define GEMM_BLOCKS (M_PAD / 64)  // 1563
#define SM_STRIDE 264             // 256 + 8 halves pad -> conflict-free LDS
#define GEMM_SMEM (2 * 64 * SM_STRIDE * 2)   // 67584 B

// ---------------- device scratch (static, no allocation) ----------------
// invariants on entry to kernel_launch (BSS zero first call, restored each call):
//   g_cntA all zero (scanA re-zeroes), g_xd all zero (gemm re-zeroes).
__device__ int   g_cntA[N_NODES];
__device__ int   g_offA[N_NODES + 1];
__device__ int   g_curA[N_NODES];
__device__ unsigned long long g_descA[SCANA_NB];
__device__ int2  g_ent[N_EDGES];                                     // adj (val,col)
__device__ __align__(128) __half g_xd[(size_t)M_PAD * N_FEATS];      // dense X, 51.2MB
__device__ __align__(128) __half g_wt[OUT_DIM * N_FEATS];            // W^T fp16 [n][k]
__device__ __align__(128) __half g_xw[(size_t)M_PAD * OUT_DIM];      // fp16 xw

// ---------------- threefry2x32 (exact JAX replica, key = (0, 42)) -------
__device__ __forceinline__ uint32_t rotl32(uint32_t x, int r) {
    return __funnelshift_l(x, x, r);
}

__device__ __forceinline__ uint2 threefry2x32_042(uint32_t x0, uint32_t x1) {
    const uint32_t k0 = 0u;
    const uint32_t k1 = 42u;
    const uint32_t k2 = 0x1BD11BDAu ^ k0 ^ k1;
    x0 += k0; x1 += k1;
#define TF_R4(a,b,c,d) \
    x0 += x1; x1 = rotl32(x1,(a)); x1 ^= x0; \
    x0 += x1; x1 = rotl32(x1,(b)); x1 ^= x0; \
    x0 += x1; x1 = rotl32(x1,(c)); x1 ^= x0; \
    x0 += x1; x1 = rotl32(x1,(d)); x1 ^= x0;
    TF_R4(13,15,26, 6);  x0 += k1; x1 += k2 + 1u;
    TF_R4(17,29,16,24);  x0 += k2; x1 += k0 + 2u;
    TF_R4(13,15,26, 6);  x0 += k0; x1 += k1 + 3u;
    TF_R4(17,29,16,24);  x0 += k1; x1 += k2 + 4u;
    TF_R4(13,15,26, 6);  x0 += k2; x1 += k0 + 5u;
#undef TF_R4
    return make_uint2(x0, x1);
}

__device__ __forceinline__ uint32_t jax_bits_partitionable(uint32_t i) {
    uint2 r = threefry2x32_042(0u, i);
    return r.x ^ r.y;
}

__device__ __forceinline__ float bits_to_unit(uint32_t bits) {
    return __uint_as_float((bits >> 9) | 0x3f800000u) - 1.0f;
}

__device__ __forceinline__ float dropout_val(uint32_t i, float v) {
    const float SCALE = (float)(1.0 / 0.9);
    float u = bits_to_unit(jax_bits_partitionable(i));
    return (0.9f + u >= 1.0f) ? v * SCALE : 0.0f;   // == floor(0.9+u) != 0
}

// ---------------- X path: densify + tensor-core GEMM --------------------

// W [K=256][N=64] fp32 -> g_wt [n][k] fp16 (transposed)
__global__ __launch_bounds__(256) void wconv_kernel(const float* __restrict__ W) {
    int i = blockIdx.x * 256 + threadIdx.x;      // i = k*64 + n
    int k = i >> 6, n = i & 63;
    g_wt[n * N_FEATS + k] = __float2half(__ldg(&W[i]));
}

// dropout + scatter-add into dense g_xd (fp16 atomics; duplicates accumulate)
#define SQ_X (NNZ_X / 2)
__global__ __launch_bounds__(256) void scatterXd_kernel(const float* __restrict__ fv,
                                                        const int* __restrict__ frow,
                                                        const int* __restrict__ fcol) {
    int q = blockIdx.x * blockDim.x + threadIdx.x;
    if (q >= SQ_X) return;
    float2 v2 = __ldg(reinterpret_cast<const float2*>(fv) + q);
    int2   r2 = __ldg(reinterpret_cast<const int2*>(frow) + q);
    int2   c2 = __ldg(reinterpret_cast<const int2*>(fcol) + q);
    float va = dropout_val((uint32_t)(2 * q), v2.x);
    float vb = dropout_val((uint32_t)(2 * q + 1), v2.y);
    atomicAdd(&g_xd[(size_t)r2.x * N_FEATS + c2.x], __float2half(va));
    atomicAdd(&g_xd[(size_t)r2.y * N_FEATS + c2.y], __float2half(vb));
}

__device__ __forceinline__ void mma16816(float* c, uint32_t a0, uint32_t a1,
                                         uint32_t a2, uint32_t a3,
                                         uint32_t b0, uint32_t b1) {
    asm volatile(
        "mma.sync.aligned.m16n8k16.row.col.f32.f16.f16.f32 "
        "{%0,%1,%2,%3}, {%4,%5,%6,%7}, {%8,%9}, {%0,%1,%2,%3};\n"
        : "+f"(c[0]), "+f"(c[1]), "+f"(c[2]), "+f"(c[3])
        : "r"(a0), "r"(a1), "r"(a2), "r"(a3), "r"(b0), "r"(b1));
}

// dense GEMM: g_xw[m, n] = sum_k g_xd[m, k] * g_wt[n, k]
// block = 128 threads (4 warps), 64 rows; warp w -> rows 16w..16w+15, all 64 cols.
// After staging to smem, the block re-zeroes its g_xd tile (restores invariant).
__global__ __launch_bounds__(128) void gemm_kernel() {
    extern __shared__ __half sm[];
    __half* As = sm;                          // [64][SM_STRIDE]
    __half* Ws = sm + 64 * SM_STRIDE;         // [64][SM_STRIDE]
    int tid = threadIdx.x;
    size_t m0 = (size_t)blockIdx.x * 64;

    // stage A (64x256) and Wt (64x256), int4-coalesced
    for (int i = tid; i < 64 * 32; i += 128) {
        int r = i >> 5, c = i & 31;
        int4 av = *reinterpret_cast<const int4*>(&g_xd[(m0 + r) * N_FEATS + c * 8]);
        *reinterpret_cast<int4*>(&As[r * SM_STRIDE + c * 8]) = av;
        int4 wv = *reinterpret_cast<const int4*>(&g_wt[r * N_FEATS + c * 8]);
        *reinterpret_cast<int4*>(&Ws[r * SM_STRIDE + c * 8]) = wv;
    }
    __syncthreads();

    // re-zero our g_xd tile for the next call
    {
        int4 z = make_int4(0, 0, 0, 0);
        for (int i = tid; i < 64 * 32; i += 128)
            *reinterpret_cast<int4*>(&g_xd[(m0 + (i >> 5)) * N_FEATS + (i & 31) * 8]) = z;
    }

    int warp = tid >> 5, lane = tid & 31;
    int grp = lane >> 2, tig = lane & 3;
    int ar0 = warp * 16 + grp;

    float acc[8][4];
#pragma unroll
    for (int nt = 0; nt < 8; nt++)
#pragma unroll
        for (int j = 0; j < 4; j++) acc[nt][j] = 0.0f;

#pragma unroll 4
    for (int kc = 0; kc < 16; kc++) {
        int k0 = kc * 16 + 2 * tig;
        uint32_t a0 = *reinterpret_cast<uint32_t*>(&As[ar0 * SM_STRIDE + k0]);
        uint32_t a1 = *reinterpret_cast<uint32_t*>(&As[(ar0 + 8) * SM_STRIDE + k0]);
        uint32_t a2 = *reinterpret_cast<uint32_t*>(&As[ar0 * SM_STRIDE + k0 + 8]);
        uint32_t a3 = *reinterpret_cast<uint32_t*>(&As[(ar0 + 8) * SM_STRIDE + k0 + 8]);
#pragma unroll
        for (int nt = 0; nt < 8; nt++) {
            uint32_t b0 = *reinterpret_cast<uint32_t*>(&Ws[(nt * 8 + grp) * SM_STRIDE + k0]);
            uint32_t b1 = *reinterpret_cast<uint32_t*>(&Ws[(nt * 8 + grp) * SM_STRIDE + k0 + 8]);
            mma16816(acc[nt], a0, a1, a2, a3, b0, b1);
        }
    }

    // store fp16: c0,c1 -> (row ar0, cols 2tig,2tig+1); c2,c3 -> row ar0+8
    size_t row_lo = (m0 + ar0) * OUT_DIM;
    size_t row_hi = (m0 + ar0 + 8) * OUT_DIM;
#pragma unroll
    for (int nt = 0; nt < 8; nt++) {
        int col = nt * 8 + 2 * tig;
        *reinterpret_cast<__half2*>(&g_xw[row_lo + col]) =
            __floats2half2_rn(acc[nt][0], acc[nt][1]);
        *reinterpret_cast<__half2*>(&g_xw[row_hi + col]) =
            __floats2half2_rn(acc[nt][2], acc[nt][3]);
    }
}

// ---------------- A path: hist -> scan -> scatter (CSR for adj) ---------
#define HQ_A (N_EDGES / 4)
#define HBA  ((HQ_A + 255) / 256)
__global__ __launch_bounds__(256) void histA_kernel(const int* __restrict__ arow) {
    if (blockIdx.x == 0 && threadIdx.x < SCANA_NB) g_descA[threadIdx.x] = 0ULL;
    int q = blockIdx.x * blockDim.x + threadIdx.x;
    if (q < HQ_A) {
        int4 r = __ldg(reinterpret_cast<const int4*>(arow) + q);
        atomicAdd(&g_cntA[r.x], 1);
        atomicAdd(&g_cntA[r.y], 1);
        atomicAdd(&g_cntA[r.z], 1);
        atomicAdd(&g_cntA[r.w], 1);
    }
}

__global__ __launch_bounds__(SCAN_BS) void scanA_kernel() {
    __shared__ int ws[SCAN_BS / 32];
    __shared__ int s_total;
    __shared__ unsigned s_prefix;

    int b    = blockIdx.x;
    int tid  = threadIdx.x;
    int lane = tid & 31, wid = tid >> 5;
    int tbase = b * SCAN_CHUNK + tid * SCAN_EL;

    int v[SCAN_EL];
    {
        int4 z = make_int4(0, 0, 0, 0);
#pragma unroll
        for (int h = 0; h < 2; h++) {
            int idx = tbase + h * 4;
            if (idx < N_NODES) {
                int4 a = *reinterpret_cast<int4*>(&g_cntA[idx]);
                *reinterpret_cast<int4*>(&g_cntA[idx]) = z;
                v[h * 4 + 0] = a.x; v[h * 4 + 1] = a.y;
                v[h * 4 + 2] = a.z; v[h * 4 + 3] = a.w;
            } else {
                v[h * 4 + 0] = v[h * 4 + 1] = v[h * 4 + 2] = v[h * 4 + 3] = 0;
            }
        }
    }

    int pre[SCAN_EL];
    int s = 0;
#pragma unroll
    for (int k = 0; k < SCAN_EL; k++) { pre[k] = s; s += v[k]; }

    int x = s;
#pragma unroll
    for (int d = 1; d < 32; d <<= 1) {
        int y = __shfl_up_sync(0xFFFFFFFFu, x, d);
        if (lane >= d) x += y;
    }
    if (lane == 31) ws[wid] = x;
    __syncthreads();
    if (tid == 0) {
        int acc = 0;
#pragma unroll
        for (int k = 0; k < SCAN_BS / 32; k++) { int t = ws[k]; ws[k] = acc; acc += t; }
        s_total = acc;
    }
    __syncthreads();

    if (wid == 0) {
        unsigned total = (unsigned)s_total;
        if (b == 0) {
            if (lane == 0) {
                atomicExch(&g_descA[0], ((unsigned long long)total << 32) | 2ULL);
                s_prefix = 0u;
            }
        } else {
            if (lane == 0)
                atomicExch(&g_descA[b], ((unsigned long long)total << 32) | 1ULL);
            unsigned running = 0;
            int hb = b;
            while (true) {
                int j = hb - 1 - lane;
                unsigned long long d64;
                if (j >= 0) {
                    do { d64 = atomicAdd(&g_descA[j], 0ULL); } while ((d64 & 3ULL) == 0ULL);
                } else {
                    d64 = 2ULL;
                }
                unsigned st  = (unsigned)(d64 & 3ULL);
                unsigned val = (unsigned)(d64 >> 32);
                unsigned pm  = __ballot_sync(0xFFFFFFFFu, st == 2u);
                if (pm) {
                    int L = __ffs(pm) - 1;
                    unsigned c = (lane <= L) ? val : 0u;
#pragma unroll
                    for (int d = 16; d; d >>= 1) c += __shfl_xor_sync(0xFFFFFFFFu, c, d);
                    running += c;
                    break;
                } else {
                    unsigned c = val;
#pragma unroll
                    for (int d = 16; d; d >>= 1) c += __shfl_xor_sync(0xFFFFFFFFu, c, d);
                    running += c;
                    hb -= 32;
                }
            }
            if (lane == 0) {
                atomicExch(&g_descA[b],
                           ((unsigned long long)(running + total) << 32) | 2ULL);
                s_prefix = running;
            }
        }
    }
    __syncthreads();

    int base = (int)s_prefix + (x - s) + ws[wid];
#pragma unroll
    for (int k = 0; k < SCAN_EL; k++) {
        int idx = tbase + k;
        if (idx < N_NODES) {
            int t = base + pre[k];
            g_offA[idx] = t;
            g_curA[idx] = t;
        }
    }
    if (b == 0 && tid == 0) g_offA[N_NODES] = N_EDGES;
}

#define SQ_A (N_EDGES / 2)
__global__ __launch_bounds__(256) void scatterA_kernel(const float* __restrict__ av,
                                                       const int* __restrict__ arow,
                                                       const int* __restrict__ acol) {
    int q = blockIdx.x * blockDim.x + threadIdx.x;
    if (q >= SQ_A) return;
    float2 v2 = __ldg(reinterpret_cast<const float2*>(av) + q);
    int2   r2 = __ldg(reinterpret_cast<const int2*>(arow) + q);
    int2   c2 = __ldg(reinterpret_cast<const int2*>(acol) + q);
    {
        int pos = atomicAdd(&g_curA[r2.x], 1);
        g_ent[pos] = make_int2(__float_as_int(v2.x), c2.x);
    }
    {
        int pos = atomicAdd(&g_curA[r2.y], 1);
        g_ent[pos] = make_int2(__float_as_int(v2.y), c2.y);
    }
}

// ---------------- SpMM2: out = relu(A @ xw), warp/row gather ------------
__global__ __launch_bounds__(256) void spmm2_kernel(float* __restrict__ out) {
    int w = blockIdx.x * 8 + (threadIdx.x >> 5);
    if (w >= N_NODES) return;
    int lane = threadIdx.x & 31;
    int s = g_offA[w], e = g_offA[w + 1];
    float ax = 0.0f, ay = 0.0f;
    for (int base = s; base < e; base += 32) {
        int2 my = make_int2(0, 0);
        if (base + lane < e) my = __ldg(&g_ent[base + lane]);
        int n = e - base; if (n > 32) n = 32;
#pragma unroll 1
        for (int k = 0; k < n; k += 4) {
            float v0 = __int_as_float(__shfl_sync(0xFFFFFFFFu, my.x, k + 0));
            int   c0 = __shfl_sync(0xFFFFFFFFu, my.y, k + 0);
            float v1 = __int_as_float(__shfl_sync(0xFFFFFFFFu, my.x, k + 1));
            int   c1 = __shfl_sync(0xFFFFFFFFu, my.y, k + 1);
            float v2 = __int_as_float(__shfl_sync(0xFFFFFFFFu, my.x, k + 2));
            int   c2 = __shfl_sync(0xFFFFFFFFu, my.y, k + 2);
            float v3 = __int_as_float(__shfl_sync(0xFFFFFFFFu, my.x, k + 3));
            int   c3 = __shfl_sync(0xFFFFFFFFu, my.y, k + 3);
            __half2 h0 = __ldg(reinterpret_cast<const __half2*>(g_xw + (size_t)c0 * OUT_DIM) + lane);
            __half2 h1 = __ldg(reinterpret_cast<const __half2*>(g_xw + (size_t)c1 * OUT_DIM) + lane);
            __half2 h2 = __ldg(reinterpret_cast<const __half2*>(g_xw + (size_t)c2 * OUT_DIM) + lane);
            __half2 h3 = __ldg(reinterpret_cast<const __half2*>(g_xw + (size_t)c3 * OUT_DIM) + lane);
            float2 f0 = __half22float2(h0);
            float2 f1 = __half22float2(h1);
            float2 f2 = __half22float2(h2);
            float2 f3 = __half22float2(h3);
            ax = fmaf(v0, f0.x, ax);  ay = fmaf(v0, f0.y, ay);
            ax = fmaf(v1, f1.x, ax);  ay = fmaf(v1, f1.y, ay);
            ax = fmaf(v2, f2.x, ax);  ay = fmaf(v2, f2.y, ay);
            ax = fmaf(v3, f3.x, ax);  ay = fmaf(v3, f3.y, ay);
        }
    }
    ax = fmaxf(ax, 0.0f);
    ay = fmaxf(ay, 0.0f);
    reinterpret_cast<float2*>(out + (size_t)w * OUT_DIM)[lane] = make_float2(ax, ay);
}

// ---------------- launch -------------------------------------------------
extern "C" void kernel_launch(void* const* d_in, const int* in_sizes, int n_in,
                              void* d_out, int out_size) {
    const float* fv   = (const float*)d_in[0];
    const float* W    = (const float*)d_in[1];
    const float* av   = (const float*)d_in[2];
    const int*   frow = (const int*)d_in[3];
    const int*   fcol = (const int*)d_in[4];
    const int*   arow = (const int*)d_in[5];
    const int*   acol = (const int*)d_in[6];
    float* out = (float*)d_out;

    static cudaStream_t s1 = nullptr;
    static cudaEvent_t  e_fork = nullptr, e_join = nullptr;
    if (s1 == nullptr) {
        cudaStreamCreateWithFlags(&s1, cudaStreamNonBlocking);
        cudaEventCreateWithFlags(&e_fork, cudaEventDisableTiming);
        cudaEventCreateWithFlags(&e_join, cudaEventDisableTiming);
        cudaFuncSetAttribute(gemm_kernel,
                             cudaFuncAttributeMaxDynamicSharedMemorySize, GEMM_SMEM);
    }

    // fork: A-chain on s1
    cudaEventRecord(e_fork, 0);
    cudaStreamWaitEvent(s1, e_fork, 0);
    histA_kernel<<<HBA, 256, 0, s1>>>(arow);
    scanA_kernel<<<SCANA_NB, SCAN_BS, 0, s1>>>();
    scatterA_kernel<<<(SQ_A + 255) / 256, 256, 0, s1>>>(av, arow, acol);
    cudaEventRecord(e_join, s1);

    // X-chain on launch stream: densify + tensor-core GEMM
    wconv_kernel<<<(N_FEATS * OUT_DIM) / 256, 256>>>(W);
    scatterXd_kernel<<<(SQ_X + 255) / 256, 256>>>(fv, frow, fcol);
    gemm_kernel<<<GEMM_BLOCKS, 128, GEMM_SMEM>>>();

    // join: spmm2 needs xw and the adj CSR
    cudaStreamWaitEvent(0, e_join, 0);
    spmm2_kernel<<<(N_NODES + 7) / 8, 256>>>(out);
}

// round 8
// speedup vs baseline: 1.2285x; 1.2285x over previous
#include <cuda_runtime.h>
#include <cuda_fp16.h>
#include <stdint.h>

#define N_NODES 100000
#define N_FEATS 256
#define OUT_DIM 64
#define NNZ_X   1280000
#define N_EDGES 1600000
#define TOT_NNZ (NNZ_X + N_EDGES)
#define NROWS2  (2 * N_NODES)

// scan config: 256 threads x 8 elems = 2048 per block; per-half scan
#define SCAN_BS 256
#define SCAN_EL 8
#define SCAN_CHUNK (SCAN_BS * SCAN_EL)
#define SCANH_NB ((N_NODES + SCAN_CHUNK - 1) / SCAN_CHUNK)   // 49

// ---------------- device scratch (static, no allocation) ----------------
// invariant: g_cnt all-zero on entry (BSS zero first call; scans re-zero).
__device__ int   g_cnt[NROWS2];
__device__ int   g_off[NROWS2 + 1];
__device__ int   g_cur[NROWS2];
__device__ unsigned long long g_descX[SCANH_NB];       // (value<<32)|status
__device__ unsigned long long g_descA[SCANH_NB];
__device__ int2  g_ent[TOT_NNZ];                       // packed (value_bits, col)
__device__ float g_fvd[NNZ_X];                         // dropout'd feat values
__device__ __align__(128) __half g_wh[N_FEATS * OUT_DIM];            // fp16 W copy
__device__ __align__(128) __half g_xw[(size_t)N_NODES * OUT_DIM];    // fp16 xw, 12.8MB

// ---------------- threefry2x32 (exact JAX replica, key = (0, 42)) -------
__device__ __forceinline__ uint32_t rotl32(uint32_t x, int r) {
    return __funnelshift_l(x, x, r);
}

__device__ __forceinline__ uint2 threefry2x32_042(uint32_t x0, uint32_t x1) {
    const uint32_t k0 = 0u;
    const uint32_t k1 = 42u;
    const uint32_t k2 = 0x1BD11BDAu ^ k0 ^ k1;
    x0 += k0; x1 += k1;
#define TF_R4(a,b,c,d) \
    x0 += x1; x1 = rotl32(x1,(a)); x1 ^= x0; \
    x0 += x1; x1 = rotl32(x1,(b)); x1 ^= x0; \
    x0 += x1; x1 = rotl32(x1,(c)); x1 ^= x0; \
    x0 += x1; x1 = rotl32(x1,(d)); x1 ^= x0;
    TF_R4(13,15,26, 6);  x0 += k1; x1 += k2 + 1u;
    TF_R4(17,29,16,24);  x0 += k2; x1 += k0 + 2u;
    TF_R4(13,15,26, 6);  x0 += k0; x1 += k1 + 3u;
    TF_R4(17,29,16,24);  x0 += k1; x1 += k2 + 4u;
    TF_R4(13,15,26, 6);  x0 += k2; x1 += k0 + 5u;
#undef TF_R4
    return make_uint2(x0, x1);
}

__device__ __forceinline__ uint32_t jax_bits_partitionable(uint32_t i) {
    uint2 r = threefry2x32_042(0u, i);
    return r.x ^ r.y;
}

__device__ __forceinline__ float bits_to_unit(uint32_t bits) {
    return __uint_as_float((bits >> 9) | 0x3f800000u) - 1.0f;
}

__device__ __forceinline__ float dropout_val(uint32_t i, float v) {
    const float SCALE = (float)(1.0 / 0.9);
    float u = bits_to_unit(jax_bits_partitionable(i));
    return (0.9f + u >= 1.0f) ? v * SCALE : 0.0f;   // == floor(0.9+u) != 0
}

// ---------------- dropout mask/value precompute (ALU-bound, s1) ---------
#define MQ_X (NNZ_X / 2)
__global__ __launch_bounds__(256) void mask_kernel(const float* __restrict__ fv) {
    int q = blockIdx.x * blockDim.x + threadIdx.x;
    if (q >= MQ_X) return;
    float2 v2 = __ldg(reinterpret_cast<const float2*>(fv) + q);
    float2 o;
    o.x = dropout_val((uint32_t)(2 * q), v2.x);
    o.y = dropout_val((uint32_t)(2 * q + 1), v2.y);
    *(reinterpret_cast<float2*>(g_fvd) + q) = o;
}

// ---------------- histograms (per half, int4-vectorized) ----------------
#define HQ_X   (NNZ_X / 4)
#define HBX    ((HQ_X + 255) / 256)
#define WCONV_B 8   // 8 blocks x 256 threads x 8 elems = 16384 = N_FEATS*OUT_DIM
__global__ __launch_bounds__(256) void histX_kernel(const int* __restrict__ frow,
                                                    const float* __restrict__ W) {
    if (blockIdx.x == 0 && threadIdx.x < SCANH_NB) g_descX[threadIdx.x] = 0ULL;
    if (blockIdx.x >= HBX) {
        int t = (blockIdx.x - HBX) * 256 + threadIdx.x;   // 0..2047
#pragma unroll
        for (int k = 0; k < 8; k++) {
            int i = t * 8 + k;
            g_wh[i] = __float2half(W[i]);
        }
        return;
    }
    int q = blockIdx.x * blockDim.x + threadIdx.x;
    if (q < HQ_X) {
        int4 r = __ldg(reinterpret_cast<const int4*>(frow) + q);
        atomicAdd(&g_cnt[r.x], 1);
        atomicAdd(&g_cnt[r.y], 1);
        atomicAdd(&g_cnt[r.z], 1);
        atomicAdd(&g_cnt[r.w], 1);
    }
}

#define HQ_A   (N_EDGES / 4)
#define HBA    ((HQ_A + 255) / 256)
__global__ __launch_bounds__(256) void histA_kernel(const int* __restrict__ arow) {
    if (blockIdx.x == 0 && threadIdx.x < SCANH_NB) g_descA[threadIdx.x] = 0ULL;
    int q = blockIdx.x * blockDim.x + threadIdx.x;
    if (q < HQ_A) {
        int4 r = __ldg(reinterpret_cast<const int4*>(arow) + q);
        atomicAdd(&g_cnt[N_NODES + r.x], 1);
        atomicAdd(&g_cnt[N_NODES + r.y], 1);
        atomicAdd(&g_cnt[N_NODES + r.z], 1);
        atomicAdd(&g_cnt[N_NODES + r.w], 1);
    }
}

// ---------------- per-half single-pass scan (decoupled lookback) --------
__global__ __launch_bounds__(SCAN_BS) void scan_kernel(int half) {
    __shared__ int ws[SCAN_BS / 32];
    __shared__ int s_total;
    __shared__ unsigned s_prefix;

    unsigned long long* desc = half ? g_descA : g_descX;
    int row_base  = half ? N_NODES : 0;
    int pref_base = half ? NNZ_X : 0;

    int b    = blockIdx.x;
    int tid  = threadIdx.x;
    int lane = tid & 31, wid = tid >> 5;
    int tbase = b * SCAN_CHUNK + tid * SCAN_EL;

    int v[SCAN_EL];
    {
        int4 z = make_int4(0, 0, 0, 0);
#pragma unroll
        for (int h = 0; h < 2; h++) {
            int idx = tbase + h * 4;
            if (idx < N_NODES) {
                int4 a = *reinterpret_cast<int4*>(&g_cnt[row_base + idx]);
                *reinterpret_cast<int4*>(&g_cnt[row_base + idx]) = z;
                v[h * 4 + 0] = a.x; v[h * 4 + 1] = a.y;
                v[h * 4 + 2] = a.z; v[h * 4 + 3] = a.w;
            } else {
                v[h * 4 + 0] = v[h * 4 + 1] = v[h * 4 + 2] = v[h * 4 + 3] = 0;
            }
        }
    }

    int pre[SCAN_EL];
    int s = 0;
#pragma unroll
    for (int k = 0; k < SCAN_EL; k++) { pre[k] = s; s += v[k]; }

    int x = s;
#pragma unroll
    for (int d = 1; d < 32; d <<= 1) {
        int y = __shfl_up_sync(0xFFFFFFFFu, x, d);
        if (lane >= d) x += y;
    }
    if (lane == 31) ws[wid] = x;
    __syncthreads();
    if (tid == 0) {
        int acc = 0;
#pragma unroll
        for (int k = 0; k < SCAN_BS / 32; k++) { int t = ws[k]; ws[k] = acc; acc += t; }
        s_total = acc;
    }
    __syncthreads();

    if (wid == 0) {
        unsigned total = (unsigned)s_total;
        if (b == 0) {
            if (lane == 0) {
                atomicExch(&desc[0], ((unsigned long long)total << 32) | 2ULL);
                s_prefix = 0u;
            }
        } else {
            if (lane == 0)
                atomicExch(&desc[b], ((unsigned long long)total << 32) | 1ULL);
            unsigned running = 0;
            int hb = b;
            while (true) {
                int j = hb - 1 - lane;
                unsigned long long d64;
                if (j >= 0) {
                    do { d64 = atomicAdd(&desc[j], 0ULL); } while ((d64 & 3ULL) == 0ULL);
                } else {
                    d64 = 2ULL;
                }
                unsigned st  = (unsigned)(d64 & 3ULL);
                unsigned val = (unsigned)(d64 >> 32);
                unsigned pm  = __ballot_sync(0xFFFFFFFFu, st == 2u);
                if (pm) {
                    int L = __ffs(pm) - 1;
                    unsigned c = (lane <= L) ? val : 0u;
#pragma unroll
                    for (int d = 16; d; d >>= 1) c += __shfl_xor_sync(0xFFFFFFFFu, c, d);
                    running += c;
                    break;
                } else {
                    unsigned c = val;
#pragma unroll
                    for (int d = 16; d; d >>= 1) c += __shfl_xor_sync(0xFFFFFFFFu, c, d);
                    running += c;
                    hb -= 32;
                }
            }
            if (lane == 0) {
                atomicExch(&desc[b],
                           ((unsigned long long)(running + total) << 32) | 2ULL);
                s_prefix = running;
            }
        }
    }
    __syncthreads();

    int base = pref_base + (int)s_prefix + (x - s) + ws[wid];
#pragma unroll
    for (int k = 0; k < SCAN_EL; k++) {
        int idx = tbase + k;
        if (idx < N_NODES) {
            int t = base + pre[k];
            g_off[row_base + idx] = t;
            g_cur[row_base + idx] = t;
        }
    }
    if (b == 0 && tid == 0) {
        if (half) g_off[NROWS2] = TOT_NNZ;
        else      g_off[N_NODES] = NNZ_X;
    }
}

// ---------------- scatters (per half, x2 vectorized) --------------------
#define SQ_X   (NNZ_X / 2)
__global__ __launch_bounds__(256) void scatterX_kernel(const int* __restrict__ frow,
                                                       const int* __restrict__ fcol) {
    int q = blockIdx.x * blockDim.x + threadIdx.x;
    if (q >= SQ_X) return;
    float2 v2 = *(reinterpret_cast<const float2*>(g_fvd) + q);
    int2   r2 = __ldg(reinterpret_cast<const int2*>(frow) + q);
    int2   c2 = __ldg(reinterpret_cast<const int2*>(fcol) + q);
    {
        int pos = atomicAdd(&g_cur[r2.x], 1);
        g_ent[pos] = make_int2(__float_as_int(v2.x), c2.x);
    }
    {
        int pos = atomicAdd(&g_cur[r2.y], 1);
        g_ent[pos] = make_int2(__float_as_int(v2.y), c2.y);
    }
}

#define SQ_A   (N_EDGES / 2)
__global__ __launch_bounds__(256) void scatterA_kernel(const float* __restrict__ av,
                                                       const int* __restrict__ arow,
                                                       const int* __restrict__ acol) {
    int q = blockIdx.x * blockDim.x + threadIdx.x;
    if (q >= SQ_A) return;
    float2 v2 = __ldg(reinterpret_cast<const float2*>(av) + q);
    int2   r2 = __ldg(reinterpret_cast<const int2*>(arow) + q);
    int2   c2 = __ldg(reinterpret_cast<const int2*>(acol) + q);
    {
        int pos = atomicAdd(&g_cur[N_NODES + r2.x], 1);
        g_ent[pos] = make_int2(__float_as_int(v2.x), c2.x);
    }
    {
        int pos = atomicAdd(&g_cur[N_NODES + r2.y], 1);
        g_ent[pos] = make_int2(__float_as_int(v2.y), c2.y);
    }
}

// ---------------- gather SpMM body (warp/row, half2/lane, fp32 acc) -----
template <bool RELU>
__device__ __forceinline__ void spmm_row(const __half* __restrict__ mat,
                                         int s, int e, int lane,
                                         float& ax, float& ay) {
    for (int base = s; base < e; base += 32) {
        int2 my = make_int2(0, 0);
        if (base + lane < e) my = __ldg(&g_ent[base + lane]);
        int n = e - base; if (n > 32) n = 32;
#pragma unroll 1
        for (int k = 0; k < n; k += 4) {
            float v0 = __int_as_float(__shfl_sync(0xFFFFFFFFu, my.x, k + 0));
            int   c0 = __shfl_sync(0xFFFFFFFFu, my.y, k + 0);
            float v1 = __int_as_float(__shfl_sync(0xFFFFFFFFu, my.x, k + 1));
            int   c1 = __shfl_sync(0xFFFFFFFFu, my.y, k + 1);
            float v2 = __int_as_float(__shfl_sync(0xFFFFFFFFu, my.x, k + 2));
            int   c2 = __shfl_sync(0xFFFFFFFFu, my.y, k + 2);
            float v3 = __int_as_float(__shfl_sync(0xFFFFFFFFu, my.x, k + 3));
            int   c3 = __shfl_sync(0xFFFFFFFFu, my.y, k + 3);
            __half2 h0 = __ldg(reinterpret_cast<const __half2*>(mat + (size_t)c0 * OUT_DIM) + lane);
            __half2 h1 = __ldg(reinterpret_cast<const __half2*>(mat + (size_t)c1 * OUT_DIM) + lane);
            __half2 h2 = __ldg(reinterpret_cast<const __half2*>(mat + (size_t)c2 * OUT_DIM) + lane);
            __half2 h3 = __ldg(reinterpret_cast<const __half2*>(mat + (size_t)c3 * OUT_DIM) + lane);
            float2 f0 = __half22float2(h0);
            float2 f1 = __half22float2(h1);
            float2 f2 = __half22float2(h2);
            float2 f3 = __half22float2(h3);
            ax = fmaf(v0, f0.x, ax);  ay = fmaf(v0, f0.y, ay);
            ax = fmaf(v1, f1.x, ax);  ay = fmaf(v1, f1.y, ay);
            ax = fmaf(v2, f2.x, ax);  ay = fmaf(v2, f2.y, ay);
            ax = fmaf(v3, f3.x, ax);  ay = fmaf(v3, f3.y, ay);
        }
    }
    if (RELU) { ax = fmaxf(ax, 0.0f); ay = fmaxf(ay, 0.0f); }
}

__global__ __launch_bounds__(256) void spmm1_kernel() {
    int w = blockIdx.x * 8 + (threadIdx.x >> 5);
    if (w >= N_NODES) return;
    int lane = threadIdx.x & 31;
    float ax = 0.0f, ay = 0.0f;
    spmm_row<false>(g_wh, g_off[w], g_off[w + 1], lane, ax, ay);
    reinterpret_cast<__half2*>(g_xw + (size_t)w * OUT_DIM)[lane] =
        __floats2half2_rn(ax, ay);
}

__global__ __launch_bounds__(256) void spmm2_kernel(float* __restrict__ out) {
    int w = blockIdx.x * 8 + (threadIdx.x >> 5);
    if (w >= N_NODES) return;
    int lane = threadIdx.x & 31;
    float ax = 0.0f, ay = 0.0f;
    spmm_row<true>(g_xw, g_off[N_NODES + w], g_off[N_NODES + w + 1], lane, ax, ay);
    reinterpret_cast<float2*>(out + (size_t)w * OUT_DIM)[lane] = make_float2(ax, ay);
}

// ---------------- launch (3 streams: X-chain, mask, A-chain) ------------
extern "C" void kernel_launch(void* const* d_in, const int* in_sizes, int n_in,
                              void* d_out, int out_size) {
    const float* fv   = (const float*)d_in[0];
    const float* W    = (const float*)d_in[1];
    const float* av   = (const float*)d_in[2];
    const int*   frow = (const int*)d_in[3];
    const int*   fcol = (const int*)d_in[4];
    const int*   arow = (const int*)d_in[5];
    const int*   acol = (const int*)d_in[6];
    float* out = (float*)d_out;

    // created once on the first (uncaptured) correctness call; reused after.
    static cudaStream_t s1 = nullptr, s2 = nullptr;
    static cudaEvent_t  e_fork = nullptr, e_mask = nullptr, e_joinA = nullptr;
    if (s1 == nullptr) {
        cudaStreamCreateWithFlags(&s1, cudaStreamNonBlocking);
        cudaStreamCreateWithFlags(&s2, cudaStreamNonBlocking);
        cudaEventCreateWithFlags(&e_fork, cudaEventDisableTiming);
        cudaEventCreateWithFlags(&e_mask, cudaEventDisableTiming);
        cudaEventCreateWithFlags(&e_joinA, cudaEventDisableTiming);
    }

    // fork
    cudaEventRecord(e_fork, 0);
    cudaStreamWaitEvent(s1, e_fork, 0);
    cudaStreamWaitEvent(s2, e_fork, 0);

    // s1: dropout mask/value precompute (ALU-bound)
    mask_kernel<<<(MQ_X + 255) / 256, 256, 0, s1>>>(fv);
    cudaEventRecord(e_mask, s1);

    // s2: A-chain (mem/atomic-bound)
    histA_kernel<<<HBA, 256, 0, s2>>>(arow);
    scan_kernel<<<SCANH_NB, SCAN_BS, 0, s2>>>(1);
    scatterA_kernel<<<(SQ_A + 255) / 256, 256, 0, s2>>>(av, arow, acol);
    cudaEventRecord(e_joinA, s2);

    // stream 0: X-chain
    histX_kernel<<<HBX + WCONV_B, 256>>>(frow, W);
    scan_kernel<<<SCANH_NB, SCAN_BS>>>(0);
    cudaStreamWaitEvent(0, e_mask, 0);
    scatterX_kernel<<<(SQ_X + 255) / 256, 256>>>(frow, fcol);
    spmm1_kernel<<<(N_NODES + 7) / 8, 256>>>();

    // join: spmm2 needs xw (stream 0) and adj CSR (s2)
    cudaStreamWaitEvent(0, e_joinA, 0);
    spmm2_kernel<<<(N_NODES + 7) / 8, 256>>>(out);
}

// round 9
// speedup vs baseline: 1.2548x; 1.0214x over previous
#include <cuda_runtime.h>
#include <cuda_fp16.h>
#include <stdint.h>

#define N_NODES 100000
#define N_FEATS 256
#define OUT_DIM 64
#define NNZ_X   1280000
#define N_EDGES 1600000
#define TOT_NNZ (NNZ_X + N_EDGES)
#define NROWS2  (2 * N_NODES)

// scan config: 256 threads x 8 elems = 2048 per block; per-half scan
#define SCAN_BS 256
#define SCAN_EL 8
#define SCAN_CHUNK (SCAN_BS * SCAN_EL)
#define SCANH_NB ((N_NODES + SCAN_CHUNK - 1) / SCAN_CHUNK)   // 49

// ---------------- device scratch (static, no allocation) ----------------
// invariant: g_cnt all-zero on entry (BSS zero first call; scans re-zero).
__device__ int   g_cnt[NROWS2];
__device__ int   g_off[NROWS2 + 1];
__device__ int   g_cur[NROWS2];
__device__ unsigned long long g_descX[SCANH_NB];       // (value<<32)|status
__device__ unsigned long long g_descA[SCANH_NB];
__device__ int2  g_ent[TOT_NNZ];                       // packed (value_bits, col)
__device__ __align__(128) __half g_wh[N_FEATS * OUT_DIM];            // fp16 W copy
__device__ __align__(128) __half g_xw[(size_t)N_NODES * OUT_DIM];    // fp16 xw, 12.8MB

// ---------------- threefry2x32 (exact JAX replica, key = (0, 42)) -------
__device__ __forceinline__ uint32_t rotl32(uint32_t x, int r) {
    return __funnelshift_l(x, x, r);
}

__device__ __forceinline__ uint2 threefry2x32_042(uint32_t x0, uint32_t x1) {
    const uint32_t k0 = 0u;
    const uint32_t k1 = 42u;
    const uint32_t k2 = 0x1BD11BDAu ^ k0 ^ k1;
    x0 += k0; x1 += k1;
#define TF_R4(a,b,c,d) \
    x0 += x1; x1 = rotl32(x1,(a)); x1 ^= x0; \
    x0 += x1; x1 = rotl32(x1,(b)); x1 ^= x0; \
    x0 += x1; x1 = rotl32(x1,(c)); x1 ^= x0; \
    x0 += x1; x1 = rotl32(x1,(d)); x1 ^= x0;
    TF_R4(13,15,26, 6);  x0 += k1; x1 += k2 + 1u;
    TF_R4(17,29,16,24);  x0 += k2; x1 += k0 + 2u;
    TF_R4(13,15,26, 6);  x0 += k0; x1 += k1 + 3u;
    TF_R4(17,29,16,24);  x0 += k1; x1 += k2 + 4u;
    TF_R4(13,15,26, 6);  x0 += k2; x1 += k0 + 5u;
#undef TF_R4
    return make_uint2(x0, x1);
}

__device__ __forceinline__ uint32_t jax_bits_partitionable(uint32_t i) {
    uint2 r = threefry2x32_042(0u, i);
    return r.x ^ r.y;
}

__device__ __forceinline__ float bits_to_unit(uint32_t bits) {
    return __uint_as_float((bits >> 9) | 0x3f800000u) - 1.0f;
}

__device__ __forceinline__ float dropout_val(uint32_t i, float v) {
    const float SCALE = (float)(1.0 / 0.9);
    float u = bits_to_unit(jax_bits_partitionable(i));
    return (0.9f + u >= 1.0f) ? v * SCALE : 0.0f;   // == floor(0.9+u) != 0
}

// ---------------- histograms (per half, int4-vectorized) ----------------
#define HQ_X   (NNZ_X / 4)
#define HBX    ((HQ_X + 255) / 256)
#define WCONV_B 8   // 8 blocks x 256 threads x 8 elems = 16384 = N_FEATS*OUT_DIM
__global__ __launch_bounds__(256) void histX_kernel(const int* __restrict__ frow,
                                                    const float* __restrict__ W) {
    if (blockIdx.x == 0 && threadIdx.x < SCANH_NB) g_descX[threadIdx.x] = 0ULL;
    if (blockIdx.x >= HBX) {
        int t = (blockIdx.x - HBX) * 256 + threadIdx.x;   // 0..2047
#pragma unroll
        for (int k = 0; k < 8; k++) {
            int i = t * 8 + k;
            g_wh[i] = __float2half(W[i]);
        }
        return;
    }
    int q = blockIdx.x * blockDim.x + threadIdx.x;
    if (q < HQ_X) {
        int4 r = __ldg(reinterpret_cast<const int4*>(frow) + q);
        atomicAdd(&g_cnt[r.x], 1);
        atomicAdd(&g_cnt[r.y], 1);
        atomicAdd(&g_cnt[r.z], 1);
        atomicAdd(&g_cnt[r.w], 1);
    }
}

#define HQ_A   (N_EDGES / 4)
#define HBA    ((HQ_A + 255) / 256)
__global__ __launch_bounds__(256) void histA_kernel(const int* __restrict__ arow) {
    if (blockIdx.x == 0 && threadIdx.x < SCANH_NB) g_descA[threadIdx.x] = 0ULL;
    int q = blockIdx.x * blockDim.x + threadIdx.x;
    if (q < HQ_A) {
        int4 r = __ldg(reinterpret_cast<const int4*>(arow) + q);
        atomicAdd(&g_cnt[N_NODES + r.x], 1);
        atomicAdd(&g_cnt[N_NODES + r.y], 1);
        atomicAdd(&g_cnt[N_NODES + r.z], 1);
        atomicAdd(&g_cnt[N_NODES + r.w], 1);
    }
}

// ---------------- per-half single-pass scan (decoupled lookback) --------
__global__ __launch_bounds__(SCAN_BS) void scan_kernel(int half) {
    __shared__ int ws[SCAN_BS / 32];
    __shared__ int s_total;
    __shared__ unsigned s_prefix;

    unsigned long long* desc = half ? g_descA : g_descX;
    int row_base  = half ? N_NODES : 0;
    int pref_base = half ? NNZ_X : 0;

    int b    = blockIdx.x;
    int tid  = threadIdx.x;
    int lane = tid & 31, wid = tid >> 5;
    int tbase = b * SCAN_CHUNK + tid * SCAN_EL;

    int v[SCAN_EL];
    {
        int4 z = make_int4(0, 0, 0, 0);
#pragma unroll
        for (int h = 0; h < 2; h++) {
            int idx = tbase + h * 4;
            if (idx < N_NODES) {
                int4 a = *reinterpret_cast<int4*>(&g_cnt[row_base + idx]);
                *reinterpret_cast<int4*>(&g_cnt[row_base + idx]) = z;
                v[h * 4 + 0] = a.x; v[h * 4 + 1] = a.y;
                v[h * 4 + 2] = a.z; v[h * 4 + 3] = a.w;
            } else {
                v[h * 4 + 0] = v[h * 4 + 1] = v[h * 4 + 2] = v[h * 4 + 3] = 0;
            }
        }
    }

    int pre[SCAN_EL];
    int s = 0;
#pragma unroll
    for (int k = 0; k < SCAN_EL; k++) { pre[k] = s; s += v[k]; }

    int x = s;
#pragma unroll
    for (int d = 1; d < 32; d <<= 1) {
        int y = __shfl_up_sync(0xFFFFFFFFu, x, d);
        if (lane >= d) x += y;
    }
    if (lane == 31) ws[wid] = x;
    __syncthreads();
    if (tid == 0) {
        int acc = 0;
#pragma unroll
        for (int k = 0; k < SCAN_BS / 32; k++) { int t = ws[k]; ws[k] = acc; acc += t; }
        s_total = acc;
    }
    __syncthreads();

    if (wid == 0) {
        unsigned total = (unsigned)s_total;
        if (b == 0) {
            if (lane == 0) {
                atomicExch(&desc[0], ((unsigned long long)total << 32) | 2ULL);
                s_prefix = 0u;
            }
        } else {
            if (lane == 0)
                atomicExch(&desc[b], ((unsigned long long)total << 32) | 1ULL);
            unsigned running = 0;
            int hb = b;
            while (true) {
                int j = hb - 1 - lane;
                unsigned long long d64;
                if (j >= 0) {
                    do { d64 = atomicAdd(&desc[j], 0ULL); } while ((d64 & 3ULL) == 0ULL);
                } else {
                    d64 = 2ULL;
                }
                unsigned st  = (unsigned)(d64 & 3ULL);
                unsigned val = (unsigned)(d64 >> 32);
                unsigned pm  = __ballot_sync(0xFFFFFFFFu, st == 2u);
                if (pm) {
                    int L = __ffs(pm) - 1;
                    unsigned c = (lane <= L) ? val : 0u;
#pragma unroll
                    for (int d = 16; d; d >>= 1) c += __shfl_xor_sync(0xFFFFFFFFu, c, d);
                    running += c;
                    break;
                } else {
                    unsigned c = val;
#pragma unroll
                    for (int d = 16; d; d >>= 1) c += __shfl_xor_sync(0xFFFFFFFFu, c, d);
                    running += c;
                    hb -= 32;
                }
            }
            if (lane == 0) {
                atomicExch(&desc[b],
                           ((unsigned long long)(running + total) << 32) | 2ULL);
                s_prefix = running;
            }
        }
    }
    __syncthreads();

    int base = pref_base + (int)s_prefix + (x - s) + ws[wid];
#pragma unroll
    for (int k = 0; k < SCAN_EL; k++) {
        int idx = tbase + k;
        if (idx < N_NODES) {
            int t = base + pre[k];
            g_off[row_base + idx] = t;
            g_cur[row_base + idx] = t;
        }
    }
    if (b == 0 && tid == 0) {
        if (half) g_off[NROWS2] = TOT_NNZ;
        else      g_off[N_NODES] = NNZ_X;
    }
}

// ---------------- scatters (per half, x2 vectorized) --------------------
#define SQ_X   (NNZ_X / 2)
__global__ __launch_bounds__(256) void scatterX_kernel(const float* __restrict__ fv,
                                                       const int* __restrict__ frow,
                                                       const int* __restrict__ fcol) {
    int q = blockIdx.x * blockDim.x + threadIdx.x;
    if (q >= SQ_X) return;
    float2 v2 = __ldg(reinterpret_cast<const float2*>(fv) + q);
    int2   r2 = __ldg(reinterpret_cast<const int2*>(frow) + q);
    int2   c2 = __ldg(reinterpret_cast<const int2*>(fcol) + q);
    {
        float v = dropout_val((uint32_t)(2 * q), v2.x);
        int pos = atomicAdd(&g_cur[r2.x], 1);
        g_ent[pos] = make_int2(__float_as_int(v), c2.x);
    }
    {
        float v = dropout_val((uint32_t)(2 * q + 1), v2.y);
        int pos = atomicAdd(&g_cur[r2.y], 1);
        g_ent[pos] = make_int2(__float_as_int(v), c2.y);
    }
}

#define SQ_A   (N_EDGES / 2)
__global__ __launch_bounds__(256) void scatterA_kernel(const float* __restrict__ av,
                                                       const int* __restrict__ arow,
                                                       const int* __restrict__ acol) {
    int q = blockIdx.x * blockDim.x + threadIdx.x;
    if (q >= SQ_A) return;
    float2 v2 = __ldg(reinterpret_cast<const float2*>(av) + q);
    int2   r2 = __ldg(reinterpret_cast<const int2*>(arow) + q);
    int2   c2 = __ldg(reinterpret_cast<const int2*>(acol) + q);
    {
        int pos = atomicAdd(&g_cur[N_NODES + r2.x], 1);
        g_ent[pos] = make_int2(__float_as_int(v2.x), c2.x);
    }
    {
        int pos = atomicAdd(&g_cur[N_NODES + r2.y], 1);
        g_ent[pos] = make_int2(__float_as_int(v2.y), c2.y);
    }
}

// ---------------- gather SpMM: 4 edges per LDG.128 ----------------------
// warp/row. lane = eg*8 + cg: eg selects which of 4 edges in the quad, cg
// selects 16B (8 halves) of the 128B row. One warp-wide uint4 LDG fetches 4
// edges' rows. Per-lane shfl.idx delivers (v, c). acc = float[8] per lane;
// 2-round shfl-xor reduction combines the 4 edge-subgroups at row end.
// OOB entries carry (v=0, c=0) -> no predication needed inside quads.
__device__ __forceinline__ void spmm_row4(const __half* __restrict__ mat,
                                          int s, int e, int lane,
                                          int eg, int cg, float* acc) {
    const unsigned FULL = 0xFFFFFFFFu;
    for (int base = s; base < e; base += 32) {
        int2 my = make_int2(0, 0);
        if (base + lane < e) my = __ldg(&g_ent[base + lane]);
        int n = e - base; if (n > 32) n = 32;
        for (int k = 0; k < n; k += 8) {
            float v0 = __int_as_float(__shfl_sync(FULL, my.x, k + eg));
            int   c0 = __shfl_sync(FULL, my.y, k + eg);
            float v1 = __int_as_float(__shfl_sync(FULL, my.x, k + 4 + eg));
            int   c1 = __shfl_sync(FULL, my.y, k + 4 + eg);
            uint4 h0 = __ldg(reinterpret_cast<const uint4*>(mat + (size_t)c0 * OUT_DIM + cg * 8));
            uint4 h1 = __ldg(reinterpret_cast<const uint4*>(mat + (size_t)c1 * OUT_DIM + cg * 8));
            float2 f0 = __half22float2(*reinterpret_cast<__half2*>(&h0.x));
            float2 f1 = __half22float2(*reinterpret_cast<__half2*>(&h0.y));
            float2 f2 = __half22float2(*reinterpret_cast<__half2*>(&h0.z));
            float2 f3 = __half22float2(*reinterpret_cast<__half2*>(&h0.w));
            acc[0] = fmaf(v0, f0.x, acc[0]);  acc[1] = fmaf(v0, f0.y, acc[1]);
            acc[2] = fmaf(v0, f1.x, acc[2]);  acc[3] = fmaf(v0, f1.y, acc[3]);
            acc[4] = fmaf(v0, f2.x, acc[4]);  acc[5] = fmaf(v0, f2.y, acc[5]);
            acc[6] = fmaf(v0, f3.x, acc[6]);  acc[7] = fmaf(v0, f3.y, acc[7]);
            float2 g0 = __half22float2(*reinterpret_cast<__half2*>(&h1.x));
            float2 g1 = __half22float2(*reinterpret_cast<__half2*>(&h1.y));
            float2 g2 = __half22float2(*reinterpret_cast<__half2*>(&h1.z));
            float2 g3 = __half22float2(*reinterpret_cast<__half2*>(&h1.w));
            acc[0] = fmaf(v1, g0.x, acc[0]);  acc[1] = fmaf(v1, g0.y, acc[1]);
            acc[2] = fmaf(v1, g1.x, acc[2]);  acc[3] = fmaf(v1, g1.y, acc[3]);
            acc[4] = fmaf(v1, g2.x, acc[4]);  acc[5] = fmaf(v1, g2.y, acc[5]);
            acc[6] = fmaf(v1, g3.x, acc[6]);  acc[7] = fmaf(v1, g3.y, acc[7]);
        }
    }
    // combine the 4 edge-subgroups: lanes {l, l^8, l^16, l^24}
#pragma unroll
    for (int j = 0; j < 8; j++) acc[j] += __shfl_xor_sync(FULL, acc[j], 8);
#pragma unroll
    for (int j = 0; j < 8; j++) acc[j] += __shfl_xor_sync(FULL, acc[j], 16);
}

__global__ __launch_bounds__(256) void spmm1_kernel() {
    int w = blockIdx.x * 8 + (threadIdx.x >> 5);
    if (w >= N_NODES) return;
    int lane = threadIdx.x & 31;
    int eg = lane >> 3, cg = lane & 7;
    float acc[8] = {0, 0, 0, 0, 0, 0, 0, 0};
    spmm_row4(g_wh, g_off[w], g_off[w + 1], lane, eg, cg, acc);
    if (lane < 8) {
        uint4 o;
        *reinterpret_cast<__half2*>(&o.x) = __floats2half2_rn(acc[0], acc[1]);
        *reinterpret_cast<__half2*>(&o.y) = __floats2half2_rn(acc[2], acc[3]);
        *reinterpret_cast<__half2*>(&o.z) = __floats2half2_rn(acc[4], acc[5]);
        *reinterpret_cast<__half2*>(&o.w) = __floats2half2_rn(acc[6], acc[7]);
        *reinterpret_cast<uint4*>(g_xw + (size_t)w * OUT_DIM + lane * 8) = o;
    }
}

__global__ __launch_bounds__(256) void spmm2_kernel(float* __restrict__ out) {
    int w = blockIdx.x * 8 + (threadIdx.x >> 5);
    if (w >= N_NODES) return;
    int lane = threadIdx.x & 31;
    int eg = lane >> 3, cg = lane & 7;
    float acc[8] = {0, 0, 0, 0, 0, 0, 0, 0};
    spmm_row4(g_xw, g_off[N_NODES + w], g_off[N_NODES + w + 1], lane, eg, cg, acc);
    if (lane < 8) {
        float* dst = out + (size_t)w * OUT_DIM + lane * 8;
        float4 f0, f1;
        f0.x = fmaxf(acc[0], 0.0f); f0.y = fmaxf(acc[1], 0.0f);
        f0.z = fmaxf(acc[2], 0.0f); f0.w = fmaxf(acc[3], 0.0f);
        f1.x = fmaxf(acc[4], 0.0f); f1.y = fmaxf(acc[5], 0.0f);
        f1.z = fmaxf(acc[6], 0.0f); f1.w = fmaxf(acc[7], 0.0f);
        *reinterpret_cast<float4*>(dst)     = f0;
        *reinterpret_cast<float4*>(dst + 4) = f1;
    }
}

// ---------------- launch (fork/join: A-chain on side stream) ------------
extern "C" void kernel_launch(void* const* d_in, const int* in_sizes, int n_in,
                              void* d_out, int out_size) {
    const float* fv   = (const float*)d_in[0];
    const float* W    = (const float*)d_in[1];
    const float* av   = (const float*)d_in[2];
    const int*   frow = (const int*)d_in[3];
    const int*   fcol = (const int*)d_in[4];
    const int*   arow = (const int*)d_in[5];
    const int*   acol = (const int*)d_in[6];
    float* out = (float*)d_out;

    // created once on the first (uncaptured) correctness call; reused after.
    static cudaStream_t s1 = nullptr;
    static cudaEvent_t  e_fork = nullptr, e_join = nullptr;
    if (s1 == nullptr) {
        cudaStreamCreateWithFlags(&s1, cudaStreamNonBlocking);
        cudaEventCreateWithFlags(&e_fork, cudaEventDisableTiming);
        cudaEventCreateWithFlags(&e_join, cudaEventDisableTiming);
    }

    // fork: A-chain on s1, X-chain on the launch stream
    cudaEventRecord(e_fork, 0);
    cudaStreamWaitEvent(s1, e_fork, 0);

    histX_kernel<<<HBX + WCONV_B, 256>>>(frow, W);
    histA_kernel<<<HBA, 256, 0, s1>>>(arow);

    scan_kernel<<<SCANH_NB, SCAN_BS>>>(0);
    scan_kernel<<<SCANH_NB, SCAN_BS, 0, s1>>>(1);

    scatterX_kernel<<<(SQ_X + 255) / 256, 256>>>(fv, frow, fcol);
    scatterA_kernel<<<(SQ_A + 255) / 256, 256, 0, s1>>>(av, arow, acol);
    cudaEventRecord(e_join, s1);

    spmm1_kernel<<<(N_NODES + 7) / 8, 256>>>();

    // join: spmm2 needs xw (stream 0) and adj CSR (s1)
    cudaStreamWaitEvent(0, e_join, 0);
    spmm2_kernel<<<(N_NODES + 7) / 8, 256>>>(out);
}